// round 9
// baseline (speedup 1.0000x reference)
#include <cuda_runtime.h>
#include <cuda_bf16.h>
#include <cuda_fp16.h>
#include <mma.h>

using namespace nvcuda;

// Problem constants (GATLayer): V=100000, E=1600000, Fin=128, H=4, Cout=32
#define FIN   128
#define HC    128   // H*Cout
#define NHEAD 4
#define MAXV  100000
#define MAXE  1600000
#define SCAN_BLK 1024

// -------- scratch (static device globals; allocation-free rule) --------
__device__ __align__(16) __half g_z[MAXV * HC];       // 25.6 MB (fp16 z)
__device__ __align__(16) float g_ssrc[MAXV * NHEAD];
__device__ __align__(16) float g_sdst[MAXV * NHEAD];
__device__ int g_deg[MAXV];
__device__ int g_off[MAXV + 1];
__device__ int g_cur[MAXV];
__device__ int g_bsum[256];
__device__ int g_srcs[MAXE];
__device__ int g_is32;

// -------- helpers --------
__device__ __forceinline__ float lrelu(float v) {
    return fmaxf(v, 0.2f * v);   // branchless LeakyReLU(0.2)
}

typedef unsigned long long u64;
__device__ __forceinline__ void ffma2(u64& d, u64 a, u64 b) {
    asm("fma.rn.f32x2 %0, %1, %2, %0;" : "+l"(d) : "l"(a), "l"(b));
}
__device__ __forceinline__ u64 pack2(float x) {
    u64 r; asm("mov.b64 %0, {%1, %1};" : "=l"(r) : "f"(x)); return r;
}
__device__ __forceinline__ u64 pack2f(float lo, float hi) {
    u64 r; asm("mov.b64 %0, {%1, %2};" : "=l"(r) : "f"(lo), "f"(hi)); return r;
}
__device__ __forceinline__ void unpack2(u64 p, float& lo, float& hi) {
    asm("mov.b64 {%0, %1}, %2;" : "=f"(lo), "=f"(hi) : "l"(p));
}

// ======================================================================
// probe + deg-zero (fused): int64 edge_index has all odd 32-bit words 0
// ======================================================================
__global__ void flag_reset_kernel() {
    if (threadIdx.x == 0) g_is32 = 0;
}

__global__ void detect_zero_kernel(const unsigned int* __restrict__ w,
                                   int n_words, int V) {
    int i = blockIdx.x * blockDim.x + threadIdx.x;
    int j = 2 * i + 1;
    if (j < n_words && w[j] != 0u) g_is32 = 1;
    if (i < V) g_deg[i] = 0;
}

// ======================================================================
// CSR build
// ======================================================================
__global__ void hist_kernel(const void* __restrict__ ei, int E) {
    int e = blockIdx.x * blockDim.x + threadIdx.x;
    if (e >= E) return;
    int dst;
    if (g_is32) dst = ((const int*)ei)[E + e];
    else        dst = (int)((const long long*)ei)[(long long)E + e];
    atomicAdd(&g_deg[dst], 1);
}

__global__ void scan_reduce_kernel(int V) {
    __shared__ int sh[SCAN_BLK];
    int t = threadIdx.x;
    int v = blockIdx.x * SCAN_BLK + t;
    sh[t] = (v < V) ? g_deg[v] : 0;
    __syncthreads();
#pragma unroll
    for (int s = SCAN_BLK / 2; s > 0; s >>= 1) {
        if (t < s) sh[t] += sh[t + s];
        __syncthreads();
    }
    if (t == 0) g_bsum[blockIdx.x] = sh[0];
}

__global__ void scan_sums_kernel(int nb) {
    __shared__ int sh[128];
    int t = threadIdx.x;
    int x = (t < nb) ? g_bsum[t] : 0;
    sh[t] = x;
    __syncthreads();
#pragma unroll
    for (int off = 1; off < 128; off <<= 1) {
        int v = (t >= off) ? sh[t - off] : 0;
        __syncthreads();
        sh[t] += v;
        __syncthreads();
    }
    if (t < nb) g_bsum[t] = sh[t] - x;   // exclusive
}

__global__ void scan_final_kernel(int V) {
    __shared__ int sh[SCAN_BLK];
    int t = threadIdx.x;
    int v = blockIdx.x * SCAN_BLK + t;
    int x = (v < V) ? g_deg[v] : 0;
    sh[t] = x;
    __syncthreads();
#pragma unroll
    for (int off = 1; off < SCAN_BLK; off <<= 1) {
        int u = (t >= off) ? sh[t - off] : 0;
        __syncthreads();
        sh[t] += u;
        __syncthreads();
    }
    int excl = sh[t] - x + g_bsum[blockIdx.x];
    if (v < V) {
        g_off[v] = excl;
        g_cur[v] = excl;
        if (v == V - 1) g_off[V] = excl + x;
    }
}

__global__ void scatter_kernel(const void* __restrict__ ei, int E) {
    int e = blockIdx.x * blockDim.x + threadIdx.x;
    if (e >= E) return;
    int src, dst;
    if (g_is32) {
        const int* p = (const int*)ei;
        src = p[e]; dst = p[E + e];
    } else {
        const long long* p = (const long long*)ei;
        src = (int)p[e]; dst = (int)p[(long long)E + e];
    }
    int pos = atomicAdd(&g_cur[dst], 1);
    g_srcs[pos] = src;
}

// ======================================================================
// GEMM: z = x @ W via fp16 tensor cores (HMMA, fp32 accumulate).
// BM=64, BN=128(full), BK=16, 256 threads = 8 warps.
// Warp w = (wr=w>>2, wc=w&3) computes rows [wr*32,+32) x cols [wc*32,+32)
// as 2x2 wmma 16x16x16 frags. Epilogue: frags -> per-warp smem scratch,
// per-lane row read -> head score (warp col block == one head) + fp16 z.
// ======================================================================
#define BM 64
#define BK 16
#define XPAD 8
#define WPAD 8
#define SLD 36

__global__ void __launch_bounds__(256, 1)
gemm_kernel(const float* __restrict__ x,
            const float* __restrict__ W,
            const float* __restrict__ a_src,
            const float* __restrict__ a_dst, int V) {
    __shared__ __align__(16) __half xs[BM][BK + XPAD];
    __shared__ __align__(16) __half Wsm[BK][HC + WPAD];
    __shared__ __align__(16) float scratch[8][32][SLD];

    int tid = threadIdx.x;
    int wid = tid >> 5, lane = tid & 31;
    int wr = wid >> 2, wc = wid & 3;
    int row0 = blockIdx.x * BM;

    wmma::fragment<wmma::accumulator, 16, 16, 16, float> cf[2][2];
#pragma unroll
    for (int i = 0; i < 2; i++)
#pragma unroll
        for (int j = 0; j < 2; j++) wmma::fill_fragment(cf[i][j], 0.f);

    for (int kb = 0; kb < FIN; kb += BK) {
        {
            int r = tid >> 2, c4 = tid & 3;
            float4 v = make_float4(0.f, 0.f, 0.f, 0.f);
            if (row0 + r < V)
                v = *(const float4*)&x[(size_t)(row0 + r) * FIN + kb + c4 * 4];
            __half2* dp = (__half2*)&xs[r][c4 * 4];
            dp[0] = __floats2half2_rn(v.x, v.y);
            dp[1] = __floats2half2_rn(v.z, v.w);
        }
#pragma unroll
        for (int i = 0; i < 2; i++) {
            int f = i * 256 + tid;
            int r = f >> 5, c4 = f & 31;
            float4 v = *(const float4*)&W[(kb + r) * HC + c4 * 4];
            __half2* dp = (__half2*)&Wsm[r][c4 * 4];
            dp[0] = __floats2half2_rn(v.x, v.y);
            dp[1] = __floats2half2_rn(v.z, v.w);
        }
        __syncthreads();

        wmma::fragment<wmma::matrix_a, 16, 16, 16, __half, wmma::row_major> af[2];
        wmma::fragment<wmma::matrix_b, 16, 16, 16, __half, wmma::row_major> bf[2];
#pragma unroll
        for (int i = 0; i < 2; i++)
            wmma::load_matrix_sync(af[i], &xs[wr * 32 + i * 16][0], BK + XPAD);
#pragma unroll
        for (int j = 0; j < 2; j++)
            wmma::load_matrix_sync(bf[j], &Wsm[0][wc * 32 + j * 16], HC + WPAD);
#pragma unroll
        for (int i = 0; i < 2; i++)
#pragma unroll
            for (int j = 0; j < 2; j++)
                wmma::mma_sync(cf[i][j], af[i], bf[j], cf[i][j]);
        __syncthreads();
    }

#pragma unroll
    for (int i = 0; i < 2; i++)
#pragma unroll
        for (int j = 0; j < 2; j++)
            wmma::store_matrix_sync(&scratch[wid][i * 16][j * 16], cf[i][j],
                                    SLD, wmma::mem_row_major);
    __syncwarp();

    int h = wc;
    int r = row0 + wr * 32 + lane;

    float vals[32];
#pragma unroll
    for (int q = 0; q < 8; q++) {
        float4 v = *(float4*)&scratch[wid][lane][q * 4];
        vals[q * 4 + 0] = v.x; vals[q * 4 + 1] = v.y;
        vals[q * 4 + 2] = v.z; vals[q * 4 + 3] = v.w;
    }
    float ps = 0.f, pd = 0.f;
#pragma unroll
    for (int c = 0; c < 32; c++) {
        ps += vals[c] * __ldg(&a_src[h * 32 + c]);
        pd += vals[c] * __ldg(&a_dst[h * 32 + c]);
    }

    if (r < V) {
        __half2 hp[16];
#pragma unroll
        for (int q = 0; q < 16; q++)
            hp[q] = __floats2half2_rn(vals[2 * q], vals[2 * q + 1]);
        uint4* dst = (uint4*)&g_z[(size_t)r * HC + wc * 32];
#pragma unroll
        for (int q = 0; q < 4; q++) dst[q] = ((uint4*)hp)[q];
        g_ssrc[r * 4 + h] = ps;
        g_sdst[r * 4 + h] = pd;
    }
}

// ======================================================================
// Aggregation: TWO warps per dst vertex (each owns 64 of 128 channels),
// unroll-8 CSR walk. Lane handles one half2 (2 channels, 4B z load ->
// 128B contiguous per warp per edge = 1 L1 wavefront). Halved per-warp
// serial load chain + 2x warp count for latency hiding. den redundant
// per 16-lane head group (free). Fused normalize + ELU.
// ======================================================================
__global__ void agg_kernel(float* __restrict__ out, int V) {
    int gw = (blockIdx.x * blockDim.x + threadIdx.x) >> 5;
    int lane = threadIdx.x & 31;
    int d = gw >> 1;
    int half = gw & 1;
    if (d >= V) return;

    int beg = g_off[d], end = g_off[d + 1];
    int h = (half << 1) | (lane >> 4);        // head for my 2 channels
    int cbase = half * 64 + lane * 2;         // channel offset
    float sd = g_sdst[d * 4 + h];

    u64 acc = 0ull;                            // 2 packed fp32 channels
    float den = 0.f;

    int e = beg;
    for (; e + 8 <= end; e += 8) {
        int s[8];
#pragma unroll
        for (int t = 0; t < 8; t++) s[t] = __ldg(&g_srcs[e + t]);  // broadcast
#pragma unroll
        for (int t = 0; t < 8; t++) {
            float w = __expf(lrelu(__ldg(&g_ssrc[s[t] * 4 + h]) + sd));
            den += w;
            unsigned int raw = *(const unsigned int*)
                &g_z[(size_t)s[t] * HC + cbase];
            float2 f = __half22float2(*(__half2*)&raw);
            ffma2(acc, pack2(w), pack2f(f.x, f.y));
        }
    }
    for (; e < end; e++) {
        int s = __ldg(&g_srcs[e]);
        float w = __expf(lrelu(__ldg(&g_ssrc[s * 4 + h]) + sd));
        den += w;
        unsigned int raw = *(const unsigned int*)&g_z[(size_t)s * HC + cbase];
        float2 f = __half22float2(*(__half2*)&raw);
        ffma2(acc, pack2(w), pack2f(f.x, f.y));
    }

    float a0, a1;
    unpack2(acc, a0, a1);
    float inv = 1.f / (den + 1e-9f);
    a0 *= inv; a1 *= inv;
    a0 = a0 > 0.f ? a0 : expm1f(a0);
    a1 = a1 > 0.f ? a1 : expm1f(a1);
    *(float2*)&out[(size_t)d * HC + cbase] = make_float2(a0, a1);
}

// ======================================================================
extern "C" void kernel_launch(void* const* d_in, const int* in_sizes, int n_in,
                              void* d_out, int out_size) {
    const float* x     = (const float*)d_in[0];
    const void*  ei    = d_in[1];
    const float* W     = (const float*)d_in[2];
    const float* a_src = (const float*)d_in[3];
    const float* a_dst = (const float*)d_in[4];
    float* out = (float*)d_out;

    int V = in_sizes[0] / FIN;
    int E = in_sizes[1] / 2;
    int nb = (V + SCAN_BLK - 1) / SCAN_BLK;

    // Side stream + fork/join events (created per call; kernel_launch only
    // runs a few times — eager + capture. No device memory involved.)
    cudaStream_t s1;
    cudaStreamCreateWithFlags(&s1, cudaStreamNonBlocking);
    cudaEvent_t ev_fork, ev_join;
    cudaEventCreateWithFlags(&ev_fork, cudaEventDisableTiming);
    cudaEventCreateWithFlags(&ev_join, cudaEventDisableTiming);

    // fork: side stream handles the entire edge/CSR pipeline
    cudaEventRecord(ev_fork, 0);
    cudaStreamWaitEvent(s1, ev_fork, 0);

    int scan_words = 2 * E;
    if (scan_words > 262144) scan_words = 262144;
    int dz_threads = (V > scan_words / 2) ? V : scan_words / 2;

    flag_reset_kernel<<<1, 32, 0, s1>>>();
    detect_zero_kernel<<<(dz_threads + 255) / 256, 256, 0, s1>>>(
        (const unsigned int*)ei, scan_words, V);
    hist_kernel<<<(E + 255) / 256, 256, 0, s1>>>(ei, E);
    scan_reduce_kernel<<<nb, SCAN_BLK, 0, s1>>>(V);
    scan_sums_kernel<<<1, 128, 0, s1>>>(nb);
    scan_final_kernel<<<nb, SCAN_BLK, 0, s1>>>(V);
    scatter_kernel<<<(E + 255) / 256, 256, 0, s1>>>(ei, E);

    // main stream: tensor-core GEMM + attention scores
    gemm_kernel<<<(V + BM - 1) / BM, 256>>>(x, W, a_src, a_dst, V);

    // join: agg needs both CSR and z/scores
    cudaEventRecord(ev_join, s1);
    cudaStreamWaitEvent(0, ev_join, 0);

    // two warps per dst (channel halves)
    agg_kernel<<<(2 * V + 7) / 8, 256>>>(out, V);
}

// round 10
// speedup vs baseline: 1.2642x; 1.2642x over previous
#include <cuda_runtime.h>
#include <cuda_bf16.h>
#include <cuda_fp16.h>
#include <mma.h>

using namespace nvcuda;

// Problem constants (GATLayer): V=100000, E=1600000, Fin=128, H=4, Cout=32
#define FIN   128
#define HC    128   // H*Cout
#define NHEAD 4
#define MAXV  100000
#define MAXE  1600000
#define SCAN_BLK 1024

// -------- scratch (static device globals; allocation-free rule) --------
__device__ __align__(16) __half g_z[MAXV * HC];       // 25.6 MB (fp16 z)
__device__ __align__(16) float g_ssrc[MAXV * NHEAD];
__device__ __align__(16) float g_sdst[MAXV * NHEAD];
__device__ int g_deg[MAXV];
__device__ int g_off[MAXV + 1];
__device__ int g_cur[MAXV];
__device__ int g_bsum[256];
__device__ int g_srcs[MAXE];
__device__ int g_is32;

// -------- helpers --------
__device__ __forceinline__ float lrelu(float v) {
    return fmaxf(v, 0.2f * v);   // branchless LeakyReLU(0.2)
}

typedef unsigned long long u64;
__device__ __forceinline__ void ffma2(u64& d, u64 a, u64 b) {
    asm("fma.rn.f32x2 %0, %1, %2, %0;" : "+l"(d) : "l"(a), "l"(b));
}
__device__ __forceinline__ u64 pack2(float x) {
    u64 r; asm("mov.b64 %0, {%1, %1};" : "=l"(r) : "f"(x)); return r;
}
__device__ __forceinline__ u64 pack2f(float lo, float hi) {
    u64 r; asm("mov.b64 %0, {%1, %2};" : "=l"(r) : "f"(lo), "f"(hi)); return r;
}
__device__ __forceinline__ void unpack2(u64 p, float& lo, float& hi) {
    asm("mov.b64 {%0, %1}, %2;" : "=f"(lo), "=f"(hi) : "l"(p));
}

// ======================================================================
// probe + deg-zero (fused): int64 edge_index has all odd 32-bit words 0
// ======================================================================
__global__ void flag_reset_kernel() {
    if (threadIdx.x == 0) g_is32 = 0;
}

__global__ void detect_zero_kernel(const unsigned int* __restrict__ w,
                                   int n_words, int V) {
    int i = blockIdx.x * blockDim.x + threadIdx.x;
    int j = 2 * i + 1;
    if (j < n_words && w[j] != 0u) g_is32 = 1;
    if (i < V) g_deg[i] = 0;
}

// ======================================================================
// CSR build — hist/scatter vectorized: 2 edges per thread
// ======================================================================
__global__ void hist_kernel(const void* __restrict__ ei, int E) {
    int i = blockIdx.x * blockDim.x + threadIdx.x;   // pair index
    int e = 2 * i;
    if (e >= E) return;
    int d0, d1;
    if (g_is32) {
        int2 p = *(const int2*)((const int*)ei + E + e);      // 8B aligned (E even)
        d0 = p.x; d1 = p.y;
    } else {
        longlong2 p = *(const longlong2*)((const long long*)ei + E + e); // 16B aligned
        d0 = (int)p.x; d1 = (int)p.y;
    }
    atomicAdd(&g_deg[d0], 1);
    if (e + 1 < E) atomicAdd(&g_deg[d1], 1);
}

// P1: per-block reduce of deg -> g_bsum[b]
__global__ void scan_reduce_kernel(int V) {
    __shared__ int sh[SCAN_BLK];
    int t = threadIdx.x;
    int v = blockIdx.x * SCAN_BLK + t;
    sh[t] = (v < V) ? g_deg[v] : 0;
    __syncthreads();
#pragma unroll
    for (int s = SCAN_BLK / 2; s > 0; s >>= 1) {
        if (t < s) sh[t] += sh[t + s];
        __syncthreads();
    }
    if (t == 0) g_bsum[blockIdx.x] = sh[0];
}

// P2 (fused former scan_sums): per-block exclusive scan of deg; block
// offset computed in-kernel by reducing bsum[t < bid] (nb <= 128).
__global__ void scan_final_kernel(int V, int nb) {
    __shared__ int sh[SCAN_BLK];
    __shared__ int boff;
    int t = threadIdx.x;
    int bid = blockIdx.x;

    // block offset: sum of bsum[0..bid) — redundant tiny reduce per block
    if (t < 32) {
        int acc = 0;
        for (int q = t; q < nb; q += 32)
            if (q < bid) acc += g_bsum[q];
#pragma unroll
        for (int o = 16; o > 0; o >>= 1)
            acc += __shfl_down_sync(0xffffffffu, acc, o);
        if (t == 0) boff = acc;
    }

    int v = bid * SCAN_BLK + t;
    int x = (v < V) ? g_deg[v] : 0;
    sh[t] = x;
    __syncthreads();
#pragma unroll
    for (int off = 1; off < SCAN_BLK; off <<= 1) {
        int u = (t >= off) ? sh[t - off] : 0;
        __syncthreads();
        sh[t] += u;
        __syncthreads();
    }
    int excl = sh[t] - x + boff;
    if (v < V) {
        g_off[v] = excl;
        g_cur[v] = excl;
        if (v == V - 1) g_off[V] = excl + x;
    }
}

__global__ void scatter_kernel(const void* __restrict__ ei, int E) {
    int i = blockIdx.x * blockDim.x + threadIdx.x;   // pair index
    int e = 2 * i;
    if (e >= E) return;
    int s0, s1, d0, d1;
    if (g_is32) {
        const int* p = (const int*)ei;
        int2 sp = *(const int2*)(p + e);
        int2 dp = *(const int2*)(p + E + e);
        s0 = sp.x; s1 = sp.y; d0 = dp.x; d1 = dp.y;
    } else {
        const long long* p = (const long long*)ei;
        longlong2 sp = *(const longlong2*)(p + e);
        longlong2 dp = *(const longlong2*)(p + E + e);
        s0 = (int)sp.x; s1 = (int)sp.y; d0 = (int)dp.x; d1 = (int)dp.y;
    }
    g_srcs[atomicAdd(&g_cur[d0], 1)] = s0;
    if (e + 1 < E) g_srcs[atomicAdd(&g_cur[d1], 1)] = s1;
}

// ======================================================================
// GEMM: z = x @ W via fp16 tensor cores (HMMA, fp32 accumulate).
// BM=64, BN=128(full), BK=16, 256 threads = 8 warps.
// Warp (wr,wc): rows [wr*32,+32) x cols [wc*32,+32) as 2x2 wmma frags.
// Epilogue: frags -> per-warp smem scratch, per-lane row read ->
// head score (warp col block == one head) + fp16 z write.
// ======================================================================
#define BM 64
#define BK 16
#define XPAD 8
#define WPAD 8
#define SLD 36

__global__ void __launch_bounds__(256, 1)
gemm_kernel(const float* __restrict__ x,
            const float* __restrict__ W,
            const float* __restrict__ a_src,
            const float* __restrict__ a_dst, int V) {
    __shared__ __align__(16) __half xs[BM][BK + XPAD];
    __shared__ __align__(16) __half Wsm[BK][HC + WPAD];
    __shared__ __align__(16) float scratch[8][32][SLD];

    int tid = threadIdx.x;
    int wid = tid >> 5, lane = tid & 31;
    int wr = wid >> 2, wc = wid & 3;
    int row0 = blockIdx.x * BM;

    wmma::fragment<wmma::accumulator, 16, 16, 16, float> cf[2][2];
#pragma unroll
    for (int i = 0; i < 2; i++)
#pragma unroll
        for (int j = 0; j < 2; j++) wmma::fill_fragment(cf[i][j], 0.f);

    for (int kb = 0; kb < FIN; kb += BK) {
        {
            int r = tid >> 2, c4 = tid & 3;
            float4 v = make_float4(0.f, 0.f, 0.f, 0.f);
            if (row0 + r < V)
                v = *(const float4*)&x[(size_t)(row0 + r) * FIN + kb + c4 * 4];
            __half2* dp = (__half2*)&xs[r][c4 * 4];
            dp[0] = __floats2half2_rn(v.x, v.y);
            dp[1] = __floats2half2_rn(v.z, v.w);
        }
#pragma unroll
        for (int i = 0; i < 2; i++) {
            int f = i * 256 + tid;
            int r = f >> 5, c4 = f & 31;
            float4 v = *(const float4*)&W[(kb + r) * HC + c4 * 4];
            __half2* dp = (__half2*)&Wsm[r][c4 * 4];
            dp[0] = __floats2half2_rn(v.x, v.y);
            dp[1] = __floats2half2_rn(v.z, v.w);
        }
        __syncthreads();

        wmma::fragment<wmma::matrix_a, 16, 16, 16, __half, wmma::row_major> af[2];
        wmma::fragment<wmma::matrix_b, 16, 16, 16, __half, wmma::row_major> bf[2];
#pragma unroll
        for (int i = 0; i < 2; i++)
            wmma::load_matrix_sync(af[i], &xs[wr * 32 + i * 16][0], BK + XPAD);
#pragma unroll
        for (int j = 0; j < 2; j++)
            wmma::load_matrix_sync(bf[j], &Wsm[0][wc * 32 + j * 16], HC + WPAD);
#pragma unroll
        for (int i = 0; i < 2; i++)
#pragma unroll
            for (int j = 0; j < 2; j++)
                wmma::mma_sync(cf[i][j], af[i], bf[j], cf[i][j]);
        __syncthreads();
    }

#pragma unroll
    for (int i = 0; i < 2; i++)
#pragma unroll
        for (int j = 0; j < 2; j++)
            wmma::store_matrix_sync(&scratch[wid][i * 16][j * 16], cf[i][j],
                                    SLD, wmma::mem_row_major);
    __syncwarp();

    int h = wc;
    int r = row0 + wr * 32 + lane;

    float vals[32];
#pragma unroll
    for (int q = 0; q < 8; q++) {
        float4 v = *(float4*)&scratch[wid][lane][q * 4];
        vals[q * 4 + 0] = v.x; vals[q * 4 + 1] = v.y;
        vals[q * 4 + 2] = v.z; vals[q * 4 + 3] = v.w;
    }
    float ps = 0.f, pd = 0.f;
#pragma unroll
    for (int c = 0; c < 32; c++) {
        ps += vals[c] * __ldg(&a_src[h * 32 + c]);
        pd += vals[c] * __ldg(&a_dst[h * 32 + c]);
    }

    if (r < V) {
        __half2 hp[16];
#pragma unroll
        for (int q = 0; q < 16; q++)
            hp[q] = __floats2half2_rn(vals[2 * q], vals[2 * q + 1]);
        uint4* dst = (uint4*)&g_z[(size_t)r * HC + wc * 32];
#pragma unroll
        for (int q = 0; q < 4; q++) dst[q] = ((uint4*)hp)[q];
        g_ssrc[r * 4 + h] = ps;
        g_sdst[r * 4 + h] = pd;
    }
}

// ======================================================================
// Aggregation: ONE warp per dst (R8 winner), unroll-8 CSR walk.
// Broadcast srcs loads, fp16 z gather (256B/warp/edge), packed f32x2
// accumulate, fused softmax-normalize + ELU. Unroll 8 halves the
// dependent-load windows vs unroll 4 (deg~16 -> 2 windows).
// ======================================================================
__global__ void agg_kernel(float* __restrict__ out, int V) {
    int d = (blockIdx.x * blockDim.x + threadIdx.x) >> 5;
    int lane = threadIdx.x & 31;
    if (d >= V) return;

    int beg = g_off[d], end = g_off[d + 1];
    int h = lane >> 3;
    float sd = g_sdst[d * 4 + h];

    u64 acc01 = 0ull, acc23 = 0ull;
    float den = 0.f;

    int e = beg;
    for (; e + 8 <= end; e += 8) {
        int s[8];
#pragma unroll
        for (int t = 0; t < 8; t++) s[t] = __ldg(&g_srcs[e + t]);  // broadcast
#pragma unroll
        for (int t = 0; t < 8; t++) {
            float w = __expf(lrelu(__ldg(&g_ssrc[s[t] * 4 + h]) + sd));
            den += w;
            u64 wp = pack2(w);
            uint2 raw = *(const uint2*)&g_z[(size_t)s[t] * HC + lane * 4];
            float2 f0 = __half22float2(*(__half2*)&raw.x);
            float2 f1 = __half22float2(*(__half2*)&raw.y);
            ffma2(acc01, wp, pack2f(f0.x, f0.y));
            ffma2(acc23, wp, pack2f(f1.x, f1.y));
        }
    }
    for (; e < end; e++) {
        int s = __ldg(&g_srcs[e]);
        float w = __expf(lrelu(__ldg(&g_ssrc[s * 4 + h]) + sd));
        den += w;
        u64 wp = pack2(w);
        uint2 raw = *(const uint2*)&g_z[(size_t)s * HC + lane * 4];
        float2 f0 = __half22float2(*(__half2*)&raw.x);
        float2 f1 = __half22float2(*(__half2*)&raw.y);
        ffma2(acc01, wp, pack2f(f0.x, f0.y));
        ffma2(acc23, wp, pack2f(f1.x, f1.y));
    }

    float4 acc;
    unpack2(acc01, acc.x, acc.y);
    unpack2(acc23, acc.z, acc.w);

    float inv = 1.f / (den + 1e-9f);
    acc.x *= inv; acc.y *= inv; acc.z *= inv; acc.w *= inv;
    acc.x = acc.x > 0.f ? acc.x : expm1f(acc.x);
    acc.y = acc.y > 0.f ? acc.y : expm1f(acc.y);
    acc.z = acc.z > 0.f ? acc.z : expm1f(acc.z);
    acc.w = acc.w > 0.f ? acc.w : expm1f(acc.w);
    *(float4*)&out[(size_t)d * HC + lane * 4] = acc;
}

// ======================================================================
extern "C" void kernel_launch(void* const* d_in, const int* in_sizes, int n_in,
                              void* d_out, int out_size) {
    const float* x     = (const float*)d_in[0];
    const void*  ei    = d_in[1];
    const float* W     = (const float*)d_in[2];
    const float* a_src = (const float*)d_in[3];
    const float* a_dst = (const float*)d_in[4];
    float* out = (float*)d_out;

    int V = in_sizes[0] / FIN;
    int E = in_sizes[1] / 2;
    int nb = (V + SCAN_BLK - 1) / SCAN_BLK;

    // Side stream + fork/join events (created per call; kernel_launch only
    // runs a few times — eager + capture. No device memory involved.)
    cudaStream_t s1;
    cudaStreamCreateWithFlags(&s1, cudaStreamNonBlocking);
    cudaEvent_t ev_fork, ev_join;
    cudaEventCreateWithFlags(&ev_fork, cudaEventDisableTiming);
    cudaEventCreateWithFlags(&ev_join, cudaEventDisableTiming);

    // fork: side stream handles the entire edge/CSR pipeline
    cudaEventRecord(ev_fork, 0);
    cudaStreamWaitEvent(s1, ev_fork, 0);

    int scan_words = 2 * E;
    if (scan_words > 262144) scan_words = 262144;
    int dz_threads = (V > scan_words / 2) ? V : scan_words / 2;

    flag_reset_kernel<<<1, 32, 0, s1>>>();
    detect_zero_kernel<<<(dz_threads + 255) / 256, 256, 0, s1>>>(
        (const unsigned int*)ei, scan_words, V);
    int pairs = (E + 1) / 2;
    hist_kernel<<<(pairs + 255) / 256, 256, 0, s1>>>(ei, E);
    scan_reduce_kernel<<<nb, SCAN_BLK, 0, s1>>>(V);
    scan_final_kernel<<<nb, SCAN_BLK, 0, s1>>>(V, nb);
    scatter_kernel<<<(pairs + 255) / 256, 256, 0, s1>>>(ei, E);

    // main stream: tensor-core GEMM + attention scores
    gemm_kernel<<<(V + BM - 1) / BM, 256>>>(x, W, a_src, a_dst, V);

    // join: agg needs both CSR and z/scores
    cudaEventRecord(ev_join, s1);
    cudaStreamWaitEvent(0, ev_join, 0);

    agg_kernel<<<(V + 7) / 8, 256>>>(out, V);
}